// round 1
// baseline (speedup 1.0000x reference)
#include <cuda_runtime.h>
#include <math_constants.h>

// Causal attention: B=4, S=4096, D=64, fp32.
// Flash-style: CTA = 64 query rows of one batch; 128 threads = 2 per row
// (each owns 32 of the 64 dims). K/V tiles of 64 keys staged in smem.
// Two-phase per tile: (A) scores -> smem + running row max, (B) exp + P@V
// with a single O-rescale per tile.

#define NB 4
#define NS 4096
#define ND 64
#define QT 64
#define KT 64
#define HD 32           // dims per thread (half of D)
#define NTHREADS 128

__global__ void __launch_bounds__(NTHREADS)
attn_fwd_kernel(const float* __restrict__ Q,
                const float* __restrict__ K,
                const float* __restrict__ V,
                float* __restrict__ O)
{
    __shared__ float ks[KT][ND];    // 16 KB
    __shared__ float vs[KT][ND];    // 16 KB
    __shared__ float ss[KT][QT];    // 16 KB  scores, [key][row] -> conflict-free

    const int tid = threadIdx.x;
    const int r   = tid >> 1;       // query row within tile (0..63)
    const int h   = tid & 1;        // which 32-dim half
    const int bid = blockIdx.x;
    const int b   = bid % NB;
    const int qt  = (NS / QT - 1) - (bid / NB);   // longest tiles first

    const float scale = 0.125f;     // 1/sqrt(64)

    // q row-half into registers, pre-scaled
    float qreg[HD];
    {
        const float* qp = Q + ((size_t)b * NS + (size_t)qt * QT + r) * ND + h * HD;
        #pragma unroll
        for (int i = 0; i < HD / 4; ++i) {
            float4 t = *reinterpret_cast<const float4*>(qp + 4 * i);
            qreg[4 * i + 0] = t.x * scale;
            qreg[4 * i + 1] = t.y * scale;
            qreg[4 * i + 2] = t.z * scale;
            qreg[4 * i + 3] = t.w * scale;
        }
    }

    float oreg[HD];
    #pragma unroll
    for (int i = 0; i < HD; ++i) oreg[i] = 0.0f;
    float m = -CUDART_INF_F;
    float l = 0.0f;

    const int nkt = qt + 1;         // causal: key tiles 0..qt
    for (int kt = 0; kt < nkt; ++kt) {
        __syncthreads();            // previous tile fully consumed
        // cooperative K/V tile load: 1024 float4 each, coalesced
        {
            const float4* kg = reinterpret_cast<const float4*>(
                K + ((size_t)b * NS + (size_t)kt * KT) * ND);
            const float4* vg = reinterpret_cast<const float4*>(
                V + ((size_t)b * NS + (size_t)kt * KT) * ND);
            float4* ksm = reinterpret_cast<float4*>(&ks[0][0]);
            float4* vsm = reinterpret_cast<float4*>(&vs[0][0]);
            #pragma unroll
            for (int i = 0; i < (KT * ND / 4) / NTHREADS; ++i) {
                int idx = tid + i * NTHREADS;
                ksm[idx] = kg[idx];
                vsm[idx] = vg[idx];
            }
        }
        __syncthreads();

        const bool diag = (kt == qt);
        const float m_prev = m;

        // ---- Phase A: scores for 64 keys (2 at a time for ILP) ----
        for (int j = 0; j < KT; j += 2) {
            float a0 = 0.f, a1 = 0.f, a2 = 0.f, a3 = 0.f;
            float c0 = 0.f, c1 = 0.f, c2 = 0.f, c3 = 0.f;
            const float* k0 = &ks[j][h * HD];
            const float* k1 = &ks[j + 1][h * HD];
            #pragma unroll
            for (int d4 = 0; d4 < HD / 4; ++d4) {
                float4 x = *reinterpret_cast<const float4*>(k0 + 4 * d4);
                float4 y = *reinterpret_cast<const float4*>(k1 + 4 * d4);
                a0 = fmaf(qreg[4 * d4 + 0], x.x, a0);
                a1 = fmaf(qreg[4 * d4 + 1], x.y, a1);
                a2 = fmaf(qreg[4 * d4 + 2], x.z, a2);
                a3 = fmaf(qreg[4 * d4 + 3], x.w, a3);
                c0 = fmaf(qreg[4 * d4 + 0], y.x, c0);
                c1 = fmaf(qreg[4 * d4 + 1], y.y, c1);
                c2 = fmaf(qreg[4 * d4 + 2], y.z, c2);
                c3 = fmaf(qreg[4 * d4 + 3], y.w, c3);
            }
            float s0p = (a0 + a1) + (a2 + a3);
            float s1p = (c0 + c1) + (c2 + c3);
            // combine the two 32-dim halves (partner lane = lane ^ 1)
            float s0 = s0p + __shfl_xor_sync(0xffffffffu, s0p, 1);
            float s1 = s1p + __shfl_xor_sync(0xffffffffu, s1p, 1);
            if (diag) {
                if (j     > r) s0 = -CUDART_INF_F;
                if (j + 1 > r) s1 = -CUDART_INF_F;
            }
            if (h == 0) {           // one writer per row; readers are same warp
                ss[j][r]     = s0;
                ss[j + 1][r] = s1;
            }
            m = fmaxf(m, fmaxf(s0, s1));
        }
        __syncwarp();               // ss visibility within the warp

        // ---- rescale previous accumulator once per tile ----
        float corr = __expf(m_prev - m);   // exp(-inf)=0 on first tile
        l *= corr;
        #pragma unroll
        for (int i = 0; i < HD; ++i) oreg[i] *= corr;

        // ---- Phase B: p = exp(s - m); o += p * V ----
        for (int j = 0; j < KT; ++j) {
            float p = __expf(ss[j][r] - m);   // masked keys: exp(-inf)=0
            l += p;
            const float* vr = &vs[j][h * HD];
            #pragma unroll
            for (int d4 = 0; d4 < HD / 4; ++d4) {
                float4 x = *reinterpret_cast<const float4*>(vr + 4 * d4);
                oreg[4 * d4 + 0] = fmaf(p, x.x, oreg[4 * d4 + 0]);
                oreg[4 * d4 + 1] = fmaf(p, x.y, oreg[4 * d4 + 1]);
                oreg[4 * d4 + 2] = fmaf(p, x.z, oreg[4 * d4 + 2]);
                oreg[4 * d4 + 3] = fmaf(p, x.w, oreg[4 * d4 + 3]);
            }
        }
    }

    const float inv_l = 1.0f / l;
    float* op = O + ((size_t)b * NS + (size_t)qt * QT + r) * ND + h * HD;
    #pragma unroll
    for (int i = 0; i < HD / 4; ++i) {
        float4 t;
        t.x = oreg[4 * i + 0] * inv_l;
        t.y = oreg[4 * i + 1] * inv_l;
        t.z = oreg[4 * i + 2] * inv_l;
        t.w = oreg[4 * i + 3] * inv_l;
        *reinterpret_cast<float4*>(op + 4 * i) = t;
    }
}

extern "C" void kernel_launch(void* const* d_in, const int* in_sizes, int n_in,
                              void* d_out, int out_size)
{
    const float* q = (const float*)d_in[0];
    const float* k = (const float*)d_in[1];
    const float* v = (const float*)d_in[2];
    float* o = (float*)d_out;

    dim3 grid(NB * (NS / QT));   // 256 CTAs
    attn_fwd_kernel<<<grid, NTHREADS>>>(q, k, v, o);
}

// round 2
// speedup vs baseline: 1.0028x; 1.0028x over previous
#include <cuda_runtime.h>
#include <math_constants.h>

// Causal attention: B=4, S=4096, D=64, fp32.
// Flash-style: CTA = 64 query rows of one batch; 128 threads = 2 per row
// (each owns 32 of the 64 dims). K/V tiles of 64 keys staged in smem.
// Two-phase per tile: (A) scores -> smem + running row max, (B) exp + P@V
// with a single O-rescale per tile.

#define NB 4
#define NS 4096
#define ND 64
#define QT 64
#define KT 64
#define HD 32           // dims per thread (half of D)
#define NTHREADS 128

__global__ void __launch_bounds__(NTHREADS)
attn_fwd_kernel(const float* __restrict__ Q,
                const float* __restrict__ K,
                const float* __restrict__ V,
                float* __restrict__ O)
{
    __shared__ float ks[KT][ND];    // 16 KB
    __shared__ float vs[KT][ND];    // 16 KB
    __shared__ float ss[KT][QT];    // 16 KB  scores, [key][row] -> conflict-free

    const int tid = threadIdx.x;
    const int r   = tid >> 1;       // query row within tile (0..63)
    const int h   = tid & 1;        // which 32-dim half
    const int bid = blockIdx.x;
    const int b   = bid % NB;
    const int qt  = (NS / QT - 1) - (bid / NB);   // longest tiles first

    const float scale = 0.125f;     // 1/sqrt(64)

    // q row-half into registers, pre-scaled
    float qreg[HD];
    {
        const float* qp = Q + ((size_t)b * NS + (size_t)qt * QT + r) * ND + h * HD;
        #pragma unroll
        for (int i = 0; i < HD / 4; ++i) {
            float4 t = *reinterpret_cast<const float4*>(qp + 4 * i);
            qreg[4 * i + 0] = t.x * scale;
            qreg[4 * i + 1] = t.y * scale;
            qreg[4 * i + 2] = t.z * scale;
            qreg[4 * i + 3] = t.w * scale;
        }
    }

    float oreg[HD];
    #pragma unroll
    for (int i = 0; i < HD; ++i) oreg[i] = 0.0f;
    float m = -CUDART_INF_F;
    float l = 0.0f;

    const int nkt = qt + 1;         // causal: key tiles 0..qt
    for (int kt = 0; kt < nkt; ++kt) {
        __syncthreads();            // previous tile fully consumed
        // cooperative K/V tile load: 1024 float4 each, coalesced
        {
            const float4* kg = reinterpret_cast<const float4*>(
                K + ((size_t)b * NS + (size_t)kt * KT) * ND);
            const float4* vg = reinterpret_cast<const float4*>(
                V + ((size_t)b * NS + (size_t)kt * KT) * ND);
            float4* ksm = reinterpret_cast<float4*>(&ks[0][0]);
            float4* vsm = reinterpret_cast<float4*>(&vs[0][0]);
            #pragma unroll
            for (int i = 0; i < (KT * ND / 4) / NTHREADS; ++i) {
                int idx = tid + i * NTHREADS;
                ksm[idx] = kg[idx];
                vsm[idx] = vg[idx];
            }
        }
        __syncthreads();

        const bool diag = (kt == qt);
        const float m_prev = m;

        // ---- Phase A: scores for 64 keys (2 at a time for ILP) ----
        for (int j = 0; j < KT; j += 2) {
            float a0 = 0.f, a1 = 0.f, a2 = 0.f, a3 = 0.f;
            float c0 = 0.f, c1 = 0.f, c2 = 0.f, c3 = 0.f;
            const float* k0 = &ks[j][h * HD];
            const float* k1 = &ks[j + 1][h * HD];
            #pragma unroll
            for (int d4 = 0; d4 < HD / 4; ++d4) {
                float4 x = *reinterpret_cast<const float4*>(k0 + 4 * d4);
                float4 y = *reinterpret_cast<const float4*>(k1 + 4 * d4);
                a0 = fmaf(qreg[4 * d4 + 0], x.x, a0);
                a1 = fmaf(qreg[4 * d4 + 1], x.y, a1);
                a2 = fmaf(qreg[4 * d4 + 2], x.z, a2);
                a3 = fmaf(qreg[4 * d4 + 3], x.w, a3);
                c0 = fmaf(qreg[4 * d4 + 0], y.x, c0);
                c1 = fmaf(qreg[4 * d4 + 1], y.y, c1);
                c2 = fmaf(qreg[4 * d4 + 2], y.z, c2);
                c3 = fmaf(qreg[4 * d4 + 3], y.w, c3);
            }
            float s0p = (a0 + a1) + (a2 + a3);
            float s1p = (c0 + c1) + (c2 + c3);
            // combine the two 32-dim halves (partner lane = lane ^ 1)
            float s0 = s0p + __shfl_xor_sync(0xffffffffu, s0p, 1);
            float s1 = s1p + __shfl_xor_sync(0xffffffffu, s1p, 1);
            if (diag) {
                if (j     > r) s0 = -CUDART_INF_F;
                if (j + 1 > r) s1 = -CUDART_INF_F;
            }
            if (h == 0) {           // one writer per row; readers are same warp
                ss[j][r]     = s0;
                ss[j + 1][r] = s1;
            }
            m = fmaxf(m, fmaxf(s0, s1));
        }
        __syncwarp();               // ss visibility within the warp

        // ---- rescale previous accumulator once per tile ----
        float corr = __expf(m_prev - m);   // exp(-inf)=0 on first tile
        l *= corr;
        #pragma unroll
        for (int i = 0; i < HD; ++i) oreg[i] *= corr;

        // ---- Phase B: p = exp(s - m); o += p * V ----
        for (int j = 0; j < KT; ++j) {
            float p = __expf(ss[j][r] - m);   // masked keys: exp(-inf)=0
            l += p;
            const float* vr = &vs[j][h * HD];
            #pragma unroll
            for (int d4 = 0; d4 < HD / 4; ++d4) {
                float4 x = *reinterpret_cast<const float4*>(vr + 4 * d4);
                oreg[4 * d4 + 0] = fmaf(p, x.x, oreg[4 * d4 + 0]);
                oreg[4 * d4 + 1] = fmaf(p, x.y, oreg[4 * d4 + 1]);
                oreg[4 * d4 + 2] = fmaf(p, x.z, oreg[4 * d4 + 2]);
                oreg[4 * d4 + 3] = fmaf(p, x.w, oreg[4 * d4 + 3]);
            }
        }
    }

    const float inv_l = 1.0f / l;
    float* op = O + ((size_t)b * NS + (size_t)qt * QT + r) * ND + h * HD;
    #pragma unroll
    for (int i = 0; i < HD / 4; ++i) {
        float4 t;
        t.x = oreg[4 * i + 0] * inv_l;
        t.y = oreg[4 * i + 1] * inv_l;
        t.z = oreg[4 * i + 2] * inv_l;
        t.w = oreg[4 * i + 3] * inv_l;
        *reinterpret_cast<float4*>(op + 4 * i) = t;
    }
}

extern "C" void kernel_launch(void* const* d_in, const int* in_sizes, int n_in,
                              void* d_out, int out_size)
{
    const float* q = (const float*)d_in[0];
    const float* k = (const float*)d_in[1];
    const float* v = (const float*)d_in[2];
    float* o = (float*)d_out;

    dim3 grid(NB * (NS / QT));   // 256 CTAs
    attn_fwd_kernel<<<grid, NTHREADS>>>(q, k, v, o);
}